// round 12
// baseline (speedup 1.0000x reference)
#include <cuda_runtime.h>
#include <cuda_bf16.h>
#include <math.h>
#include <stdint.h>

// D_IN=42, H=800, L=256, B=16, ALPHA=20
#define LSEQ 256
#define HN   800
#define NB   16
#define G4   3200
#define NCTA 148
#define CPD  74
#define SWS  804
#define MAXR 44
#define SH_OFF (MAXR*SWS)
#define LSTM_SMEM_BYTES ((MAXR*SWS + 16*SWS)*4)   // 192960 B

// ---------------- scratch (device globals; no allocations allowed) ----------
static __device__ float g_g0[2*LSEQ*G4*NB];
static __device__ float g_g1[2*LSEQ*G4*NB];
static __device__ float g_h1[LSEQ*NB*1600];
static __device__ float g_h2[LSEQ*NB*1600];
static __device__ float g_hping[2*2*NB*HN];
static __device__ float g_ang[LSEQ*NB*3];
static __device__ unsigned g_bar[1024];           // [dir*CPD+lc] epoch flags
// bf16-split operands for tensor-core gemm1
static __device__ __nv_bfloat16 g_whi[2*G4*1600];
static __device__ __nv_bfloat16 g_wlo[2*G4*1600];
static __device__ __nv_bfloat16 g_hhi[4096*1600];
static __device__ __nv_bfloat16 g_hlo[4096*1600];

__device__ __forceinline__ float sigf(float x){ return 1.0f/(1.0f+expf(-x)); }

__device__ __forceinline__ unsigned long long ffma2(unsigned long long a,
                                                    unsigned long long b,
                                                    unsigned long long c){
    unsigned long long d;
    asm("fma.rn.f32x2 %0, %1, %2, %3;" : "=l"(d) : "l"(a), "l"(b), "l"(c));
    return d;
}
__device__ __forceinline__ uint32_t s2u(const void* p){
    uint32_t a;
    asm("{ .reg .u64 t; cvta.to.shared.u64 t, %1; cvt.u32.u64 %0, t; }"
        : "=r"(a) : "l"(p));
    return a;
}
__device__ __forceinline__ void ldm4(uint32_t* r, uint32_t addr){
    asm volatile("ldmatrix.sync.aligned.m8n8.x4.shared.b16 {%0,%1,%2,%3}, [%4];"
        : "=r"(r[0]),"=r"(r[1]),"=r"(r[2]),"=r"(r[3]) : "r"(addr));
}
__device__ __forceinline__ void mma16816(float* d, const uint32_t* a, const uint32_t* b){
    asm volatile("mma.sync.aligned.m16n8k16.row.col.f32.bf16.bf16.f32 "
        "{%0,%1,%2,%3}, {%4,%5,%6,%7}, {%8,%9}, {%0,%1,%2,%3};"
        : "+f"(d[0]),"+f"(d[1]),"+f"(d[2]),"+f"(d[3])
        : "r"(a[0]),"r"(a[1]),"r"(a[2]),"r"(a[3]), "r"(b[0]),"r"(b[1]));
}

// ---------------- per-direction flag barrier (no atomics) -------------------
__device__ __forceinline__ void gbar(int dir, int lc, unsigned e){
    __syncthreads();
    if (threadIdx.x == 0){
        __threadfence();
        *((volatile unsigned*)&g_bar[dir*CPD + lc]) = e;
    }
    if (threadIdx.x < CPD){
        volatile unsigned* f = &g_bar[dir*CPD + threadIdx.x];
        while (*f < e) { }
    }
    __syncthreads();
}

// ---------------- kernel 1: layer-0 input projection (K=42) -----------------
__global__ void proj0_kernel(const float* __restrict__ x,
                             const float* __restrict__ wih,
                             const float* __restrict__ bias){
    const int t = blockIdx.x, dir = blockIdx.y;
    const int tid = threadIdx.x;
    __shared__ float sx[16*42];
    if (t == 0 && dir == 0){
        for (int i = tid; i < 1024; i += 256) g_bar[i] = 0u;   // reset flags
    }
    for (int i = tid; i < 16*42; i += 256){
        int bb = i / 42, d = i - bb*42;
        sx[i] = x[(bb*LSEQ + t)*42 + d];
    }
    __syncthreads();
    for (int j = tid; j < G4; j += 256){
        const float* w = &wih[(dir*G4 + j)*42];
        float wr[42];
#pragma unroll
        for (int d = 0; d < 42; d++) wr[d] = w[d];
        float bv = bias[dir*G4 + j];
        float* gout = &g_g0[(((size_t)dir*LSEQ + t)*G4 + j)*NB];
        for (int bb = 0; bb < 16; bb++){
            float acc = bv;
#pragma unroll
            for (int d = 0; d < 42; d++) acc = fmaf(wr[d], sx[bb*42 + d], acc);
            gout[bb] = acc;
        }
    }
}

// ---------------- kernel 2: persistent bi-LSTM (wavefront-optimized) --------
// 148 CTAs; CTA owns 10-11 hidden units (40-44 gate rows, zero-padded to 44).
// Warp w: rg = w>>2 (row half: 22 rows), bgq = w&3 (4 batches).
// Lane: kq = lane>>2 (k phase 0..7), bi = lane&3 (batch within group).
__global__ void __launch_bounds__(256,1) lstm_kernel(
    const float* __restrict__ whh, int layer, int ebase)
{
    extern __shared__ float dsm[];
    __shared__ float sgate[MAXR*16];
    __shared__ float sc[176];

    const float* gin  = layer ? g_g1 : g_g0;
    float*       hseq = layer ? g_h2 : g_h1;

    const int cta = blockIdx.x;
    const int dir = cta / CPD;
    const int lc  = cta - dir*CPD;
    const int u0  = (lc*HN)/CPD;
    const int n_u = ((lc+1)*HN)/CPD - u0;
    const int n_rows = 4*n_u;
    const int tid = threadIdx.x;

    float* sw = dsm;
    float* sh = dsm + SH_OFF;

    // preload w into smem, zero-pad rows n_rows..43
    for (int i = tid; i < MAXR*200; i += 256){
        int r = i / 200, k4 = i - r*200;
        float4 v = make_float4(0.f,0.f,0.f,0.f);
        if (r < n_rows){
            int q = r & 3, uu = r >> 2;
            int j = q*HN + u0 + uu;
            v = *(const float4*)&whh[((size_t)(dir*G4 + j))*HN + k4*4];
        }
        *(float4*)&sw[r*SWS + k4*4] = v;
    }
    if (tid < n_u*16){
        sc[tid] = 0.f;
        g_hping[(dir*NB + (tid & 15))*HN + u0 + (tid >> 4)] = 0.f;
    }
    gbar(dir, lc, ebase + 1);

    const int warp = tid >> 5, lane = tid & 31;
    const int kq = lane >> 2, bi = lane & 3;
    const int rg = warp >> 2, bgq = warp & 3;
    const int b  = bgq*4 + bi;
    const int r0 = rg*22;
    const ulonglong2* hrow = (const ulonglong2*)&sh[b*SWS];
    const float* swb = &sw[r0*SWS];

    int p = 0;
    for (int s = 0; s < LSEQ; s++){
        const int t = dir ? (LSEQ-1-s) : s;
        // broadcast h (16x800) into smem from global ping buffer (L2-coherent)
        for (int idx = tid; idx < 3200; idx += 256){
            int bb = idx / 200, k4 = idx - bb*200;
            float4 v = __ldcg((const float4*)&g_hping[((p*2 + dir)*NB + bb)*HN + k4*4]);
            *(float4*)&sh[bb*SWS + k4*4] = v;
        }
        __syncthreads();

        unsigned long long acc[22];
#pragma unroll
        for (int j = 0; j < 22; j++) acc[j] = 0ull;

        for (int i = 0; i < 25; i++){
            const int k4 = i*8 + kq;
            ulonglong2 h2 = hrow[k4];
            const float* wp = swb + k4*4;
#pragma unroll
            for (int j = 0; j < 22; j++){
                ulonglong2 w2 = *(const ulonglong2*)(wp + j*SWS);
                acc[j] = ffma2(w2.x, h2.x, acc[j]);
                acc[j] = ffma2(w2.y, h2.y, acc[j]);
            }
        }
        // reduce over kq lanes (stride 4: masks 4,8,16), store to sgate
#pragma unroll
        for (int j = 0; j < 22; j++){
            float2 v = *(float2*)&acc[j];
            float sum = v.x + v.y;
            sum += __shfl_xor_sync(0xffffffffu, sum, 4);
            sum += __shfl_xor_sync(0xffffffffu, sum, 8);
            sum += __shfl_xor_sync(0xffffffffu, sum, 16);
            if (kq == 0 && (r0 + j) < n_rows) sgate[(r0 + j)*16 + b] = sum;
        }
        __syncthreads();

        if (tid < n_u*16){
            int uu = tid >> 4, bb = tid & 15;
            const float* gi = gin + ((size_t)(dir*LSEQ + t)*G4)*NB;
            size_t jb = (size_t)(u0 + uu);
            float giv = sgate[(uu*4 + 0)*16 + bb] + gi[(0*HN + jb)*NB + bb];
            float gf  = sgate[(uu*4 + 1)*16 + bb] + gi[(1*HN + jb)*NB + bb];
            float gg  = sgate[(uu*4 + 2)*16 + bb] + gi[(2*HN + jb)*NB + bb];
            float go  = sgate[(uu*4 + 3)*16 + bb] + gi[(3*HN + jb)*NB + bb];
            float c = sigf(gf)*sc[tid] + sigf(giv)*tanhf(gg);
            sc[tid] = c;
            float hv = sigf(go)*tanhf(c);
            int u = u0 + uu;
            g_hping[(((p^1)*2 + dir)*NB + bb)*HN + u] = hv;
            hseq[(t*NB + bb)*1600 + dir*HN + u] = hv;
        }
        p ^= 1;
        gbar(dir, lc, ebase + 2 + s);
    }
}

// ---------------- bf16 split conversion kernels ------------------------------
__global__ void split_w_kernel(const float* __restrict__ w){
    const int n = 2*G4*1600;
    for (int i = blockIdx.x*256 + threadIdx.x; i < n; i += gridDim.x*256){
        float v = w[i];
        __nv_bfloat16 h = __float2bfloat16(v);
        g_whi[i] = h;
        g_wlo[i] = __float2bfloat16(v - __bfloat162float(h));
    }
}
__global__ void split_h_kernel(){
    const int n = 4096*1600;
    for (int i = blockIdx.x*256 + threadIdx.x; i < n; i += gridDim.x*256){
        float v = g_h1[i];
        __nv_bfloat16 h = __float2bfloat16(v);
        g_hhi[i] = h;
        g_hlo[i] = __float2bfloat16(v - __bfloat162float(h));
    }
}

// ---------------- kernel 3: layer-1 proj via mma.sync bf16-split ------------
#define TP 72
#define TILE_ELEMS (128*TP)
#define GEMM_SMEM (4*TILE_ELEMS*2)  // 73728 B
__global__ void __launch_bounds__(256) gemm1_mma(const float* __restrict__ bias){
    extern __shared__ __nv_bfloat16 gsm[];
    __nv_bfloat16* sAh = gsm;
    __nv_bfloat16* sAl = gsm + TILE_ELEMS;
    __nv_bfloat16* sBh = gsm + 2*TILE_ELEMS;
    __nv_bfloat16* sBl = gsm + 3*TILE_ELEMS;
    const uint32_t uAh = s2u(sAh), uAl = s2u(sAl), uBh = s2u(sBh), uBl = s2u(sBl);

    const int tid  = threadIdx.x;
    const int jt   = blockIdx.x, mt = blockIdx.y, dir = blockIdx.z;
    const int warp = tid >> 5, lane = tid & 31;
    const int wj   = warp & 1;
    const int wm   = warp >> 1;

    const __nv_bfloat16* Ahi = g_whi + ((size_t)dir*G4 + jt*128)*1600;
    const __nv_bfloat16* Alo = g_wlo + ((size_t)dir*G4 + jt*128)*1600;
    const __nv_bfloat16* Bhi = g_hhi + (size_t)(mt*128)*1600;
    const __nv_bfloat16* Blo = g_hlo + (size_t)(mt*128)*1600;

    float acc[4][4][4];
#pragma unroll
    for (int i = 0; i < 4; i++)
#pragma unroll
        for (int j = 0; j < 4; j++)
#pragma unroll
            for (int q = 0; q < 4; q++) acc[i][j][q] = 0.f;

    const int a_row = wj*64 + (lane & 15);
    const int a_kg  = (lane >> 4)*8;
    const int b_row = wm*32 + (lane & 7) + ((lane >> 4) & 1)*8;
    const int b_kg  = ((lane >> 3) & 1)*8;

    const int ldr = tid >> 1;
    const int ldg = (tid & 1)*4;

    for (int c = 0; c < 25; c++){
        const int k0 = c*64;
#pragma unroll
        for (int g = 0; g < 4; g++){
            int gg = ldg + g;
            size_t go = (size_t)ldr*1600 + k0 + gg*8;
            int so = ldr*TP + gg*8;
            *(float4*)&sAh[so] = *(const float4*)&Ahi[go];
            *(float4*)&sAl[so] = *(const float4*)&Alo[go];
            *(float4*)&sBh[so] = *(const float4*)&Bhi[go];
            *(float4*)&sBl[so] = *(const float4*)&Blo[go];
        }
        __syncthreads();
#pragma unroll
        for (int ks = 0; ks < 4; ks++){
            uint32_t ah[4][4], al[4][4], bh[2][4], bl[2][4];
#pragma unroll
            for (int i = 0; i < 4; i++){
                uint32_t off = (uint32_t)((a_row + i*16)*TP + ks*16 + a_kg)*2;
                ldm4(ah[i], uAh + off);
                ldm4(al[i], uAl + off);
            }
#pragma unroll
            for (int np = 0; np < 2; np++){
                uint32_t off = (uint32_t)((b_row + np*16)*TP + ks*16 + b_kg)*2;
                ldm4(bh[np], uBh + off);
                ldm4(bl[np], uBl + off);
            }
#pragma unroll
            for (int i = 0; i < 4; i++){
#pragma unroll
                for (int n = 0; n < 4; n++){
                    const uint32_t* bhp = &bh[n >> 1][(n & 1)*2];
                    const uint32_t* blp = &bl[n >> 1][(n & 1)*2];
                    mma16816(acc[i][n], ah[i], bhp);
                    mma16816(acc[i][n], ah[i], blp);
                    mma16816(acc[i][n], al[i], bhp);
                }
            }
        }
        __syncthreads();
    }

    const int jb = jt*128 + wj*64;
    const int mb = mt*128 + wm*32;
#pragma unroll
    for (int i = 0; i < 4; i++){
        int j0 = jb + i*16 + (lane >> 2);
        float bv0 = bias[dir*G4 + j0];
        float bv1 = bias[dir*G4 + j0 + 8];
        size_t r0 = (size_t)(dir*LSEQ)*G4;
#pragma unroll
        for (int n = 0; n < 4; n++){
            int m  = mb + n*8 + 2*(lane & 3);
            int t  = m >> 4, b2 = m & 15;
            float2 v0 = make_float2(acc[i][n][0] + bv0, acc[i][n][1] + bv0);
            float2 v1 = make_float2(acc[i][n][2] + bv1, acc[i][n][3] + bv1);
            *(float2*)&g_g1[(r0 + (size_t)t*G4 + j0)*NB + b2]     = v0;
            *(float2*)&g_g1[(r0 + (size_t)t*G4 + j0 + 8)*NB + b2] = v1;
        }
    }
}

// ---------------- kernel 4: head (logits -> softmax -> angles) --------------
__global__ void head_kernel(const float* __restrict__ wlin,
                            const float* __restrict__ blin,
                            const float* __restrict__ alphabet){
    const int t = blockIdx.x;
    const int tid = threadIdx.x;   // 320 threads
    __shared__ float slog[16][20];
    __shared__ float smax[16];
    __shared__ float sexp[16][20];
    __shared__ float ssin[20][3], scos[20][3];
    if (tid < 60){
        int a = tid / 3, i = tid - a*3;
        float v = alphabet[a*3 + i];
        ssin[a][i] = sinf(v); scos[a][i] = cosf(v);
    }
    const int a = tid % 20, b = tid / 20;
    float acc = blin[a];
    const float4* hr = (const float4*)&g_h2[((size_t)(t*NB + b))*1600];
    const float4* wr = (const float4*)&wlin[(size_t)a*1600];
    for (int k = 0; k < 400; k++){
        float4 h = hr[k], w = wr[k];
        acc = fmaf(h.x, w.x, acc); acc = fmaf(h.y, w.y, acc);
        acc = fmaf(h.z, w.z, acc); acc = fmaf(h.w, w.w, acc);
    }
    slog[b][a] = acc;
    __syncthreads();
    if (tid < 16){
        float m = -1e30f;
        for (int q = 0; q < 20; q++) m = fmaxf(m, slog[tid][q]);
        smax[tid] = m;
    }
    __syncthreads();
    sexp[b][a] = expf(slog[b][a] - smax[b]);
    __syncthreads();
    if (tid < 48){
        int bb = tid / 3, i = tid - bb*3;
        float s = 0.f, c = 0.f;
        for (int q = 0; q < 20; q++){
            float pv = sexp[bb][q];
            s = fmaf(pv, ssin[q][i], s);
            c = fmaf(pv, scos[q][i], c);
        }
        g_ang[(t*NB + bb)*3 + i] = atan2f(s, c);
    }
}

// ---------------- kernel 5: sequential coordinate chain (NeRF) --------------
__global__ void coords_kernel(float* __restrict__ out){
    const int b = threadIdx.x;
    if (b >= 16) return;
    const float Rv[3] = {145.801f, 152.326f, 132.868f};
    const float Tv[3] = {2.124f, 1.941f, 2.028f};
    float cT[3], sT[3];
#pragma unroll
    for (int i = 0; i < 3; i++){ cT[i] = cosf(Tv[i]); sT[i] = sinf(Tv[i]); }
    float Ax=0.f,Ay=0.f,Az=1.f, Bx=0.f,By=1.f,Bz=0.f, Cx=1.f,Cy=0.f,Cz=0.f;
    out[(0*16+b)*3+0]=0.f; out[(0*16+b)*3+1]=0.f; out[(0*16+b)*3+2]=1.f;
    out[(1*16+b)*3+0]=0.f; out[(1*16+b)*3+1]=1.f; out[(1*16+b)*3+2]=0.f;
    out[(2*16+b)*3+0]=1.f; out[(2*16+b)*3+1]=0.f; out[(2*16+b)*3+2]=0.f;
    for (int tt = 0; tt < LSEQ; tt++){
#pragma unroll
        for (int i = 0; i < 3; i++){
            float P = g_ang[(tt*NB + b)*3 + i];
            float sp, cp; sincosf(P, &sp, &cp);
            float d2x = -Rv[i]*cT[i];
            float d2y =  Rv[i]*cp*sT[i];
            float d2z =  Rv[i]*sp*sT[i];
            float bcx = Cx-Bx, bcy = Cy-By, bcz = Cz-Bz;
            float inv = rsqrtf(bcx*bcx + bcy*bcy + bcz*bcz);
            bcx *= inv; bcy *= inv; bcz *= inv;
            float abx = Bx-Ax, aby = By-Ay, abz = Bz-Az;
            float nx = aby*bcz - abz*bcy;
            float ny = abz*bcx - abx*bcz;
            float nz = abx*bcy - aby*bcx;
            float invn = rsqrtf(nx*nx + ny*ny + nz*nz);
            nx *= invn; ny *= invn; nz *= invn;
            float mx = ny*bcz - nz*bcy;
            float my = nz*bcx - nx*bcz;
            float mz = nx*bcy - ny*bcx;
            float Dx = bcx*d2x + mx*d2y + nx*d2z + Cx;
            float Dy = bcy*d2x + my*d2y + ny*d2z + Cy;
            float Dz = bcz*d2x + mz*d2y + nz*d2z + Cz;
            int row = 3 + tt*3 + i;
            out[(row*16 + b)*3 + 0] = Dx;
            out[(row*16 + b)*3 + 1] = Dy;
            out[(row*16 + b)*3 + 2] = Dz;
            Ax=Bx; Ay=By; Az=Bz;
            Bx=Cx; By=Cy; Bz=Cz;
            Cx=Dx; Cy=Dy; Cz=Dz;
        }
    }
}

// ---------------- launch ------------------------------------------------------
extern "C" void kernel_launch(void* const* d_in, const int* in_sizes, int n_in,
                              void* d_out, int out_size){
    const float* x    = (const float*)d_in[0];
    const float* wih0 = (const float*)d_in[1];
    const float* whh0 = (const float*)d_in[2];
    const float* b0   = (const float*)d_in[3];
    const float* wih1 = (const float*)d_in[4];
    const float* whh1 = (const float*)d_in[5];
    const float* b1   = (const float*)d_in[6];
    const float* wlin = (const float*)d_in[7];
    const float* blin = (const float*)d_in[8];
    const float* alph = (const float*)d_in[9];
    float* out = (float*)d_out;

    cudaFuncSetAttribute(lstm_kernel,
                         cudaFuncAttributeMaxDynamicSharedMemorySize,
                         LSTM_SMEM_BYTES);
    cudaFuncSetAttribute(gemm1_mma,
                         cudaFuncAttributeMaxDynamicSharedMemorySize,
                         GEMM_SMEM);

    proj0_kernel<<<dim3(LSEQ,2),256>>>(x, wih0, b0);             // + flag reset
    split_w_kernel<<<1024,256>>>(wih1);
    lstm_kernel<<<NCTA,256,LSTM_SMEM_BYTES>>>(whh0, 0, 0);       // layer 0
    split_h_kernel<<<1024,256>>>();
    gemm1_mma<<<dim3(25,32,2),256,GEMM_SMEM>>>(b1);
    lstm_kernel<<<NCTA,256,LSTM_SMEM_BYTES>>>(whh1, 1, 300);     // layer 1
    head_kernel<<<LSEQ,320>>>(wlin, blin, alph);
    coords_kernel<<<1,32>>>(out);
}

// round 13
// speedup vs baseline: 1.1513x; 1.1513x over previous
#include <cuda_runtime.h>
#include <cuda_bf16.h>
#include <math.h>
#include <stdint.h>

// D_IN=42, H=800, L=256, B=16, ALPHA=20
#define LSEQ 256
#define HN   800
#define NB   16
#define G4   3200
#define NCTA 148
#define CPD  74
#define SWS  804
#define MAXR 44
#define SH_OFF (MAXR*SWS)
#define LSTM_SMEM_BYTES ((MAXR*SWS + 16*SWS)*4)   // 192960 B
#define BARSLOTS 600

// ---------------- scratch (device globals; no allocations allowed) ----------
static __device__ float g_g0[2*LSEQ*G4*NB];
static __device__ float g_g1[2*LSEQ*G4*NB];
static __device__ float g_h1[LSEQ*NB*1600];
static __device__ float g_h2[LSEQ*NB*1600];
static __device__ float g_hping[2*2*NB*HN];
static __device__ float g_ang[LSEQ*NB*3];
static __device__ unsigned g_bar[2*BARSLOTS];     // per-direction fresh-slot counters
// bf16-split operands for tensor-core gemm1
static __device__ __nv_bfloat16 g_whi[2*G4*1600];
static __device__ __nv_bfloat16 g_wlo[2*G4*1600];
static __device__ __nv_bfloat16 g_hhi[4096*1600];
static __device__ __nv_bfloat16 g_hlo[4096*1600];

__device__ __forceinline__ float sigf(float x){ return 1.0f/(1.0f+expf(-x)); }

__device__ __forceinline__ unsigned long long ffma2(unsigned long long a,
                                                    unsigned long long b,
                                                    unsigned long long c){
    unsigned long long d;
    asm("fma.rn.f32x2 %0, %1, %2, %3;" : "=l"(d) : "l"(a), "l"(b), "l"(c));
    return d;
}
__device__ __forceinline__ float hadd2(unsigned long long a){
    float2 v = *(float2*)&a; return v.x + v.y;
}
__device__ __forceinline__ uint32_t s2u(const void* p){
    uint32_t a;
    asm("{ .reg .u64 t; cvta.to.shared.u64 t, %1; cvt.u32.u64 %0, t; }"
        : "=r"(a) : "l"(p));
    return a;
}
__device__ __forceinline__ void ldm4(uint32_t* r, uint32_t addr){
    asm volatile("ldmatrix.sync.aligned.m8n8.x4.shared.b16 {%0,%1,%2,%3}, [%4];"
        : "=r"(r[0]),"=r"(r[1]),"=r"(r[2]),"=r"(r[3]) : "r"(addr));
}
__device__ __forceinline__ void mma16816(float* d, const uint32_t* a, const uint32_t* b){
    asm volatile("mma.sync.aligned.m16n8k16.row.col.f32.bf16.bf16.f32 "
        "{%0,%1,%2,%3}, {%4,%5,%6,%7}, {%8,%9}, {%0,%1,%2,%3};"
        : "+f"(d[0]),"+f"(d[1]),"+f"(d[2]),"+f"(d[3])
        : "r"(a[0]),"r"(a[1]),"r"(a[2]),"r"(a[3]), "r"(b[0]),"r"(b[1]));
}

// ------- per-direction grid barrier: red.release arrive, ld.acquire poll ----
__device__ __forceinline__ void gbar(int dir, int idx){
    __syncthreads();
    if (threadIdx.x == 0){
        unsigned* ctr = &g_bar[dir*BARSLOTS + idx];
        asm volatile("red.release.gpu.global.add.u32 [%0], %1;"
                     :: "l"(ctr), "r"(1u) : "memory");
        unsigned v;
        do {
            asm volatile("ld.acquire.gpu.global.u32 %0, [%1];"
                         : "=r"(v) : "l"(ctr) : "memory");
        } while (v < (unsigned)CPD);
    }
    __syncthreads();
}

// ---------------- kernel 1: layer-0 input projection (K=42) -----------------
__global__ void proj0_kernel(const float* __restrict__ x,
                             const float* __restrict__ wih,
                             const float* __restrict__ bias){
    const int t = blockIdx.x, dir = blockIdx.y;
    const int tid = threadIdx.x;
    __shared__ float sx[16*42];
    if (t == 0 && dir == 0){
        for (int i = tid; i < 2*BARSLOTS; i += 256) g_bar[i] = 0u;  // reset counters
    }
    for (int i = tid; i < 16*42; i += 256){
        int bb = i / 42, d = i - bb*42;
        sx[i] = x[(bb*LSEQ + t)*42 + d];
    }
    __syncthreads();
    for (int j = tid; j < G4; j += 256){
        const float* w = &wih[(dir*G4 + j)*42];
        float wr[42];
#pragma unroll
        for (int d = 0; d < 42; d++) wr[d] = w[d];
        float bv = bias[dir*G4 + j];
        float* gout = &g_g0[(((size_t)dir*LSEQ + t)*G4 + j)*NB];
        for (int bb = 0; bb < 16; bb++){
            float acc = bv;
#pragma unroll
            for (int d = 0; d < 42; d++) acc = fmaf(wr[d], sx[bb*42 + d], acc);
            gout[bb] = acc;
        }
    }
}

// ---------------- kernel 2: persistent bi-LSTM (R11-proven org) -------------
__global__ void __launch_bounds__(256,1) lstm_kernel(
    const float* __restrict__ whh, int layer, int bar_base)
{
    extern __shared__ float dsm[];
    __shared__ float sgate[MAXR*16];
    __shared__ float sc[176];

    const float* gin  = layer ? g_g1 : g_g0;
    float*       hseq = layer ? g_h2 : g_h1;

    const int cta = blockIdx.x;
    const int dir = cta / CPD;
    const int lc  = cta - dir*CPD;
    const int u0  = (lc*HN)/CPD;
    const int n_u = ((lc+1)*HN)/CPD - u0;
    const int n_rows = 4*n_u;
    const int tid = threadIdx.x;
    const int b   = tid & 15;
    const int slot= tid >> 4;

    float* sw = dsm;
    float* sh = dsm + SH_OFF;

    for (int i = tid; i < n_rows*200; i += 256){
        int r = i / 200, k4 = i - r*200;
        int q = r & 3, uu = r >> 2;
        int j = q*HN + u0 + uu;
        *(float4*)&sw[r*SWS + k4*4] =
            *(const float4*)&whh[((size_t)(dir*G4 + j))*HN + k4*4];
    }
    if (tid < n_u*16){
        sc[tid] = 0.f;
        g_hping[(dir*NB + (tid & 15))*HN + u0 + (tid >> 4)] = 0.f;
    }
    gbar(dir, bar_base);

    int nr = 0; int rofs[3]; int jrow[3];
    for (int r = slot; r < n_rows; r += 16){
        rofs[nr] = r*SWS;
        jrow[nr] = (r & 3)*HN + u0 + (r >> 2);
        nr++;
    }
    const ulonglong2* wp0 = (const ulonglong2*)&sw[rofs[0]];
    const ulonglong2* wp1 = (const ulonglong2*)&sw[rofs[1]];
    const ulonglong2* wp2 = (const ulonglong2*)&sw[rofs[(nr > 2) ? 2 : 0]];

    int p = 0;
    for (int s = 0; s < LSEQ; s++){
        const int t = dir ? (LSEQ-1-s) : s;
        for (int idx = tid; idx < 3200; idx += 256){
            int bb = idx / 200, k4 = idx - bb*200;
            float4 v = __ldcg((const float4*)&g_hping[((p*2 + dir)*NB + bb)*HN + k4*4]);
            *(float4*)&sh[bb*SWS + k4*4] = v;
        }
        __syncthreads();

        unsigned long long a00=0ull,a01=0ull,a10=0ull,a11=0ull,a20=0ull,a21=0ull;
        const ulonglong2* hp = (const ulonglong2*)&sh[b*SWS];
#pragma unroll 2
        for (int k4 = 0; k4 < 200; k4++){
            ulonglong2 h2 = hp[k4];
            ulonglong2 w0 = wp0[k4];
            a00 = ffma2(w0.x, h2.x, a00); a01 = ffma2(w0.y, h2.y, a01);
            ulonglong2 w1 = wp1[k4];
            a10 = ffma2(w1.x, h2.x, a10); a11 = ffma2(w1.y, h2.y, a11);
            ulonglong2 w2 = wp2[k4];
            a20 = ffma2(w2.x, h2.x, a20); a21 = ffma2(w2.y, h2.y, a21);
        }
        {
            const float* gi = gin + ((size_t)(dir*LSEQ + t)*G4)*NB;
            sgate[(slot)*16 + b]    = hadd2(a00) + hadd2(a01) + gi[(size_t)jrow[0]*NB + b];
            sgate[(slot+16)*16 + b] = hadd2(a10) + hadd2(a11) + gi[(size_t)jrow[1]*NB + b];
            if (nr > 2)
                sgate[(slot+32)*16 + b] = hadd2(a20) + hadd2(a21) + gi[(size_t)jrow[2]*NB + b];
        }
        __syncthreads();
        if (tid < n_u*16){
            int uu = tid >> 4, bb = tid & 15;
            float giv = sgate[(uu*4 + 0)*16 + bb];
            float gf  = sgate[(uu*4 + 1)*16 + bb];
            float gg  = sgate[(uu*4 + 2)*16 + bb];
            float go  = sgate[(uu*4 + 3)*16 + bb];
            float c = sigf(gf)*sc[tid] + sigf(giv)*tanhf(gg);
            sc[tid] = c;
            float hv = sigf(go)*tanhf(c);
            int u = u0 + uu;
            g_hping[(((p^1)*2 + dir)*NB + bb)*HN + u] = hv;
            hseq[(t*NB + bb)*1600 + dir*HN + u] = hv;
        }
        p ^= 1;
        gbar(dir, bar_base + 1 + s);
    }
}

// ---------------- bf16 split conversion kernels ------------------------------
__global__ void split_w_kernel(const float* __restrict__ w){
    const int n = 2*G4*1600;
    for (int i = blockIdx.x*256 + threadIdx.x; i < n; i += gridDim.x*256){
        float v = w[i];
        __nv_bfloat16 h = __float2bfloat16(v);
        g_whi[i] = h;
        g_wlo[i] = __float2bfloat16(v - __bfloat162float(h));
    }
}
__global__ void split_h_kernel(){
    const int n = 4096*1600;
    for (int i = blockIdx.x*256 + threadIdx.x; i < n; i += gridDim.x*256){
        float v = g_h1[i];
        __nv_bfloat16 h = __float2bfloat16(v);
        g_hhi[i] = h;
        g_hlo[i] = __float2bfloat16(v - __bfloat162float(h));
    }
}

// ---------------- kernel 3: layer-1 proj via mma.sync bf16-split ------------
#define TP 72
#define TILE_ELEMS (128*TP)
#define GEMM_SMEM (4*TILE_ELEMS*2)  // 73728 B
__global__ void __launch_bounds__(256) gemm1_mma(const float* __restrict__ bias){
    extern __shared__ __nv_bfloat16 gsm[];
    __nv_bfloat16* sAh = gsm;
    __nv_bfloat16* sAl = gsm + TILE_ELEMS;
    __nv_bfloat16* sBh = gsm + 2*TILE_ELEMS;
    __nv_bfloat16* sBl = gsm + 3*TILE_ELEMS;
    const uint32_t uAh = s2u(sAh), uAl = s2u(sAl), uBh = s2u(sBh), uBl = s2u(sBl);

    const int tid  = threadIdx.x;
    const int jt   = blockIdx.x, mt = blockIdx.y, dir = blockIdx.z;
    const int warp = tid >> 5, lane = tid & 31;
    const int wj   = warp & 1;
    const int wm   = warp >> 1;

    const __nv_bfloat16* Ahi = g_whi + ((size_t)dir*G4 + jt*128)*1600;
    const __nv_bfloat16* Alo = g_wlo + ((size_t)dir*G4 + jt*128)*1600;
    const __nv_bfloat16* Bhi = g_hhi + (size_t)(mt*128)*1600;
    const __nv_bfloat16* Blo = g_hlo + (size_t)(mt*128)*1600;

    float acc[4][4][4];
#pragma unroll
    for (int i = 0; i < 4; i++)
#pragma unroll
        for (int j = 0; j < 4; j++)
#pragma unroll
            for (int q = 0; q < 4; q++) acc[i][j][q] = 0.f;

    const int a_row = wj*64 + (lane & 15);
    const int a_kg  = (lane >> 4)*8;
    const int b_row = wm*32 + (lane & 7) + ((lane >> 4) & 1)*8;
    const int b_kg  = ((lane >> 3) & 1)*8;

    const int ldr = tid >> 1;
    const int ldg = (tid & 1)*4;

    for (int c = 0; c < 25; c++){
        const int k0 = c*64;
#pragma unroll
        for (int g = 0; g < 4; g++){
            int gg = ldg + g;
            size_t go = (size_t)ldr*1600 + k0 + gg*8;
            int so = ldr*TP + gg*8;
            *(float4*)&sAh[so] = *(const float4*)&Ahi[go];
            *(float4*)&sAl[so] = *(const float4*)&Alo[go];
            *(float4*)&sBh[so] = *(const float4*)&Bhi[go];
            *(float4*)&sBl[so] = *(const float4*)&Blo[go];
        }
        __syncthreads();
#pragma unroll
        for (int ks = 0; ks < 4; ks++){
            uint32_t ah[4][4], al[4][4], bh[2][4], bl[2][4];
#pragma unroll
            for (int i = 0; i < 4; i++){
                uint32_t off = (uint32_t)((a_row + i*16)*TP + ks*16 + a_kg)*2;
                ldm4(ah[i], uAh + off);
                ldm4(al[i], uAl + off);
            }
#pragma unroll
            for (int np = 0; np < 2; np++){
                uint32_t off = (uint32_t)((b_row + np*16)*TP + ks*16 + b_kg)*2;
                ldm4(bh[np], uBh + off);
                ldm4(bl[np], uBl + off);
            }
#pragma unroll
            for (int i = 0; i < 4; i++){
#pragma unroll
                for (int n = 0; n < 4; n++){
                    const uint32_t* bhp = &bh[n >> 1][(n & 1)*2];
                    const uint32_t* blp = &bl[n >> 1][(n & 1)*2];
                    mma16816(acc[i][n], ah[i], bhp);
                    mma16816(acc[i][n], ah[i], blp);
                    mma16816(acc[i][n], al[i], bhp);
                }
            }
        }
        __syncthreads();
    }

    const int jb = jt*128 + wj*64;
    const int mb = mt*128 + wm*32;
#pragma unroll
    for (int i = 0; i < 4; i++){
        int j0 = jb + i*16 + (lane >> 2);
        float bv0 = bias[dir*G4 + j0];
        float bv1 = bias[dir*G4 + j0 + 8];
        size_t r0 = (size_t)(dir*LSEQ)*G4;
#pragma unroll
        for (int n = 0; n < 4; n++){
            int m  = mb + n*8 + 2*(lane & 3);
            int t  = m >> 4, b2 = m & 15;
            float2 v0 = make_float2(acc[i][n][0] + bv0, acc[i][n][1] + bv0);
            float2 v1 = make_float2(acc[i][n][2] + bv1, acc[i][n][3] + bv1);
            *(float2*)&g_g1[(r0 + (size_t)t*G4 + j0)*NB + b2]     = v0;
            *(float2*)&g_g1[(r0 + (size_t)t*G4 + j0 + 8)*NB + b2] = v1;
        }
    }
}

// ---------------- kernel 4: head (logits -> softmax -> angles) --------------
__global__ void head_kernel(const float* __restrict__ wlin,
                            const float* __restrict__ blin,
                            const float* __restrict__ alphabet){
    const int t = blockIdx.x;
    const int tid = threadIdx.x;   // 320 threads
    __shared__ float slog[16][20];
    __shared__ float smax[16];
    __shared__ float sexp[16][20];
    __shared__ float ssin[20][3], scos[20][3];
    if (tid < 60){
        int a = tid / 3, i = tid - a*3;
        float v = alphabet[a*3 + i];
        ssin[a][i] = sinf(v); scos[a][i] = cosf(v);
    }
    const int a = tid % 20, b = tid / 20;
    float acc = blin[a];
    const float4* hr = (const float4*)&g_h2[((size_t)(t*NB + b))*1600];
    const float4* wr = (const float4*)&wlin[(size_t)a*1600];
    for (int k = 0; k < 400; k++){
        float4 h = hr[k], w = wr[k];
        acc = fmaf(h.x, w.x, acc); acc = fmaf(h.y, w.y, acc);
        acc = fmaf(h.z, w.z, acc); acc = fmaf(h.w, w.w, acc);
    }
    slog[b][a] = acc;
    __syncthreads();
    if (tid < 16){
        float m = -1e30f;
        for (int q = 0; q < 20; q++) m = fmaxf(m, slog[tid][q]);
        smax[tid] = m;
    }
    __syncthreads();
    sexp[b][a] = expf(slog[b][a] - smax[b]);
    __syncthreads();
    if (tid < 48){
        int bb = tid / 3, i = tid - bb*3;
        float s = 0.f, c = 0.f;
        for (int q = 0; q < 20; q++){
            float pv = sexp[bb][q];
            s = fmaf(pv, ssin[q][i], s);
            c = fmaf(pv, scos[q][i], c);
        }
        g_ang[(t*NB + bb)*3 + i] = atan2f(s, c);
    }
}

// ---------------- kernel 5: sequential coordinate chain (NeRF) --------------
__global__ void coords_kernel(float* __restrict__ out){
    const int b = threadIdx.x;
    if (b >= 16) return;
    const float Rv[3] = {145.801f, 152.326f, 132.868f};
    const float Tv[3] = {2.124f, 1.941f, 2.028f};
    float cT[3], sT[3];
#pragma unroll
    for (int i = 0; i < 3; i++){ cT[i] = cosf(Tv[i]); sT[i] = sinf(Tv[i]); }
    float Ax=0.f,Ay=0.f,Az=1.f, Bx=0.f,By=1.f,Bz=0.f, Cx=1.f,Cy=0.f,Cz=0.f;
    out[(0*16+b)*3+0]=0.f; out[(0*16+b)*3+1]=0.f; out[(0*16+b)*3+2]=1.f;
    out[(1*16+b)*3+0]=0.f; out[(1*16+b)*3+1]=1.f; out[(1*16+b)*3+2]=0.f;
    out[(2*16+b)*3+0]=1.f; out[(2*16+b)*3+1]=0.f; out[(2*16+b)*3+2]=0.f;
    for (int tt = 0; tt < LSEQ; tt++){
#pragma unroll
        for (int i = 0; i < 3; i++){
            float P = g_ang[(tt*NB + b)*3 + i];
            float sp, cp; sincosf(P, &sp, &cp);
            float d2x = -Rv[i]*cT[i];
            float d2y =  Rv[i]*cp*sT[i];
            float d2z =  Rv[i]*sp*sT[i];
            float bcx = Cx-Bx, bcy = Cy-By, bcz = Cz-Bz;
            float inv = rsqrtf(bcx*bcx + bcy*bcy + bcz*bcz);
            bcx *= inv; bcy *= inv; bcz *= inv;
            float abx = Bx-Ax, aby = By-Ay, abz = Bz-Az;
            float nx = aby*bcz - abz*bcy;
            float ny = abz*bcx - abx*bcz;
            float nz = abx*bcy - aby*bcx;
            float invn = rsqrtf(nx*nx + ny*ny + nz*nz);
            nx *= invn; ny *= invn; nz *= invn;
            float mx = ny*bcz - nz*bcy;
            float my = nz*bcx - nx*bcz;
            float mz = nx*bcy - ny*bcx;
            float Dx = bcx*d2x + mx*d2y + nx*d2z + Cx;
            float Dy = bcy*d2x + my*d2y + ny*d2z + Cy;
            float Dz = bcz*d2x + mz*d2y + nz*d2z + Cz;
            int row = 3 + tt*3 + i;
            out[(row*16 + b)*3 + 0] = Dx;
            out[(row*16 + b)*3 + 1] = Dy;
            out[(row*16 + b)*3 + 2] = Dz;
            Ax=Bx; Ay=By; Az=Bz;
            Bx=Cx; By=Cy; Bz=Cz;
            Cx=Dx; Cy=Dy; Cz=Dz;
        }
    }
}

// ---------------- launch ------------------------------------------------------
extern "C" void kernel_launch(void* const* d_in, const int* in_sizes, int n_in,
                              void* d_out, int out_size){
    const float* x    = (const float*)d_in[0];
    const float* wih0 = (const float*)d_in[1];
    const float* whh0 = (const float*)d_in[2];
    const float* b0   = (const float*)d_in[3];
    const float* wih1 = (const float*)d_in[4];
    const float* whh1 = (const float*)d_in[5];
    const float* b1   = (const float*)d_in[6];
    const float* wlin = (const float*)d_in[7];
    const float* blin = (const float*)d_in[8];
    const float* alph = (const float*)d_in[9];
    float* out = (float*)d_out;

    cudaFuncSetAttribute(lstm_kernel,
                         cudaFuncAttributeMaxDynamicSharedMemorySize,
                         LSTM_SMEM_BYTES);
    cudaFuncSetAttribute(gemm1_mma,
                         cudaFuncAttributeMaxDynamicSharedMemorySize,
                         GEMM_SMEM);

    proj0_kernel<<<dim3(LSEQ,2),256>>>(x, wih0, b0);             // + counter reset
    split_w_kernel<<<1024,256>>>(wih1);
    lstm_kernel<<<NCTA,256,LSTM_SMEM_BYTES>>>(whh0, 0, 0);       // slots 0..257
    split_h_kernel<<<1024,256>>>();
    gemm1_mma<<<dim3(25,32,2),256,GEMM_SMEM>>>(b1);
    lstm_kernel<<<NCTA,256,LSTM_SMEM_BYTES>>>(whh1, 1, 300);     // slots 300..557
    head_kernel<<<LSEQ,320>>>(wlin, blin, alph);
    coords_kernel<<<1,32>>>(out);
}

// round 15
// speedup vs baseline: 2.3678x; 2.0567x over previous
#include <cuda_runtime.h>
#include <cuda_bf16.h>
#include <math.h>
#include <stdint.h>

// D_IN=42, H=800, L=256, B=16, ALPHA=20
#define LSEQ 256
#define HN   800
#define NB   16
#define G4   3200
#define NCTA 148
#define CPD  74
#define WP   808                      // smem pitch (bf16): 1616B = 101*16 (LDSM-legal), 1616%128=80 -> conflict-free
#define LSTM_MMA_SMEM (128*WP*2 + 4*768*4 + 176*4)   // 219840 B

// ---------------- scratch (device globals; no allocations allowed) ----------
static __device__ float g_g0[2*LSEQ*G4*NB];
static __device__ float g_g1[2*LSEQ*G4*NB];
static __device__ float g_h1[LSEQ*NB*1600];
static __device__ float g_h2[LSEQ*NB*1600];
static __device__ float g_hping[2*2*NB*HN];
static __device__ float g_ang[LSEQ*NB*3];
static __device__ unsigned g_bar[1024];
// bf16-split operands for tensor-core gemm1
static __device__ __nv_bfloat16 g_whi[2*G4*1600];
static __device__ __nv_bfloat16 g_wlo[2*G4*1600];
static __device__ __nv_bfloat16 g_hhi[4096*1600];
static __device__ __nv_bfloat16 g_hlo[4096*1600];

__device__ __forceinline__ float sigf(float x){ return 1.0f/(1.0f+expf(-x)); }

__device__ __forceinline__ uint32_t s2u(const void* p){
    uint32_t a;
    asm("{ .reg .u64 t; cvta.to.shared.u64 t, %1; cvt.u32.u64 %0, t; }"
        : "=r"(a) : "l"(p));
    return a;
}
__device__ __forceinline__ void ldm4(uint32_t* r, uint32_t addr){
    asm volatile("ldmatrix.sync.aligned.m8n8.x4.shared.b16 {%0,%1,%2,%3}, [%4];"
        : "=r"(r[0]),"=r"(r[1]),"=r"(r[2]),"=r"(r[3]) : "r"(addr));
}
__device__ __forceinline__ void mma16816(float* d, const uint32_t* a, const uint32_t* b){
    asm volatile("mma.sync.aligned.m16n8k16.row.col.f32.bf16.bf16.f32 "
        "{%0,%1,%2,%3}, {%4,%5,%6,%7}, {%8,%9}, {%0,%1,%2,%3};"
        : "+f"(d[0]),"+f"(d[1]),"+f"(d[2]),"+f"(d[3])
        : "r"(a[0]),"r"(a[1]),"r"(a[2]),"r"(a[3]), "r"(b[0]),"r"(b[1]));
}

// ---------------- grid-wide barrier (R11-proven single counter) -------------
__device__ __forceinline__ void gbar(int idx){
    __syncthreads();
    if (threadIdx.x == 0){
        __threadfence();
        atomicAdd(&g_bar[idx], 1u);
        volatile unsigned* vb = &g_bar[idx];
        while (*vb < (unsigned)NCTA) { }
        __threadfence();
    }
    __syncthreads();
}

// ---------------- kernel 1: layer-0 input projection (K=42) -----------------
__global__ void proj0_kernel(const float* __restrict__ x,
                             const float* __restrict__ wih,
                             const float* __restrict__ bias){
    const int t = blockIdx.x, dir = blockIdx.y;
    const int tid = threadIdx.x;
    __shared__ float sx[16*42];
    if (t == 0 && dir == 0){
        for (int i = tid; i < 1024; i += 256) g_bar[i] = 0u;
    }
    for (int i = tid; i < 16*42; i += 256){
        int bb = i / 42, d = i - bb*42;
        sx[i] = x[(bb*LSEQ + t)*42 + d];
    }
    __syncthreads();
    for (int j = tid; j < G4; j += 256){
        const float* w = &wih[(dir*G4 + j)*42];
        float wr[42];
#pragma unroll
        for (int d = 0; d < 42; d++) wr[d] = w[d];
        float bv = bias[dir*G4 + j];
        float* gout = &g_g0[(((size_t)dir*LSEQ + t)*G4 + j)*NB];
        for (int bb = 0; bb < 16; bb++){
            float acc = bv;
#pragma unroll
            for (int d = 0; d < 42; d++) acc = fmaf(wr[d], sx[bb*42 + d], acc);
            gout[bb] = acc;
        }
    }
}

// ---------------- kernel 2: persistent bi-LSTM via mma.sync bf16-split ------
// 148 CTAs; CTA owns 10-11 units (40-44 gate rows, padded to 48).
// W in SMEM as bf16 hi/lo; A_hi fragments register-resident across all steps.
// 8 warps k-split (warps 0-1: 7 k16-tiles, warps 2-7: 6). Each warp computes
// full 48x16 partial; 2-phase smem reduction; gates as in R11.
__global__ void __launch_bounds__(256,1) lstm_mma_kernel(
    const float* __restrict__ whh, int layer, int bar_base)
{
    extern __shared__ char dsm8[];
    __nv_bfloat16* swhi = (__nv_bfloat16*)dsm8;
    __nv_bfloat16* swlo = swhi + 48*WP;
    __nv_bfloat16* shhi = swhi + 96*WP;
    __nv_bfloat16* shlo = swhi + 112*WP;
    float* fpart = (float*)(dsm8 + 128*WP*2);    // [4][768]
    float* sc    = fpart + 4*768;                // [176]

    const float* gin  = layer ? g_g1 : g_g0;
    float*       hseq = layer ? g_h2 : g_h1;

    const int cta = blockIdx.x;
    const int dir = cta / CPD;
    const int lc  = cta - dir*CPD;
    const int u0  = (lc*HN)/CPD;
    const int n_u = ((lc+1)*HN)/CPD - u0;
    const int n_rows = 4*n_u;
    const int tid = threadIdx.x;
    const int lane = tid & 31, warp = tid >> 5;

    // one-time: weights -> smem bf16 hi/lo (rows >= n_rows zeroed)
    for (int i = tid; i < 48*200; i += 256){
        int r = i/200, k4 = i - r*200;
        float4 v = make_float4(0.f,0.f,0.f,0.f);
        if (r < n_rows){
            int q = r & 3, uu = r >> 2;
            int j = q*HN + u0 + uu;
            v = *(const float4*)&whh[((size_t)(dir*G4 + j))*HN + k4*4];
        }
        __nv_bfloat162 h01 = __floats2bfloat162_rn(v.x, v.y);
        __nv_bfloat162 h23 = __floats2bfloat162_rn(v.z, v.w);
        *(__nv_bfloat162*)&swhi[r*WP + k4*4]     = h01;
        *(__nv_bfloat162*)&swhi[r*WP + k4*4 + 2] = h23;
        __nv_bfloat162 l01 = __floats2bfloat162_rn(v.x - __low2float(h01),
                                                   v.y - __high2float(h01));
        __nv_bfloat162 l23 = __floats2bfloat162_rn(v.z - __low2float(h23),
                                                   v.w - __high2float(h23));
        *(__nv_bfloat162*)&swlo[r*WP + k4*4]     = l01;
        *(__nv_bfloat162*)&swlo[r*WP + k4*4 + 2] = l23;
    }
    if (tid < n_u*16){
        sc[tid] = 0.f;
        g_hping[(dir*NB + (tid & 15))*HN + u0 + (tid >> 4)] = 0.f;
    }
    gbar(bar_base);   // includes __syncthreads: weight smem visible

    const uint32_t uWhi = s2u(swhi), uWlo = s2u(swlo);
    const uint32_t uHhi = s2u(shhi), uHlo = s2u(shlo);
    const int a_row = lane & 15;
    const int a_kg  = (lane >> 4)*8;
    const int b_row = (lane & 7) + ((lane >> 4) & 1)*8;
    const int b_kg  = ((lane >> 3) & 1)*8;
    const int myNT  = (warp < 2) ? 7 : 6;
    const int kt0   = (warp < 2) ? warp*7 : 14 + (warp - 2)*6;

    // A_hi fragments, register-resident for all 256 steps
    uint32_t afr[3][7][4];
#pragma unroll
    for (int m = 0; m < 3; m++)
#pragma unroll
        for (int i = 0; i < 7; i++)
            if (i < myNT)
                ldm4(afr[m][i],
                     uWhi + (uint32_t)(((a_row + m*16)*WP + (kt0+i)*16 + a_kg)*2));

    const int guu = tid >> 4, gbb = tid & 15;
    const bool gateT = tid < n_u*16;

    int p = 0;
    for (int s = 0; s < LSEQ; s++){
        const int t = dir ? (LSEQ-1-s) : s;
        // prefetch input projections (consumed in gate phase)
        float gi0=0.f, gi1=0.f, gi2=0.f, gi3=0.f;
        if (gateT){
            const float* gi = gin + ((size_t)(dir*LSEQ + t)*G4)*NB;
            size_t jb = (size_t)(u0 + guu);
            gi0 = gi[(0*HN + jb)*NB + gbb];
            gi1 = gi[(1*HN + jb)*NB + gbb];
            gi2 = gi[(2*HN + jb)*NB + gbb];
            gi3 = gi[(3*HN + jb)*NB + gbb];
        }
        // fill: h fp32 -> bf16 hi/lo smem
        for (int idx = tid; idx < 3200; idx += 256){
            int bb = idx/200, k4 = idx - bb*200;
            float4 v = __ldcg((const float4*)&g_hping[((p*2 + dir)*NB + bb)*HN + k4*4]);
            __nv_bfloat162 h01 = __floats2bfloat162_rn(v.x, v.y);
            __nv_bfloat162 h23 = __floats2bfloat162_rn(v.z, v.w);
            *(__nv_bfloat162*)&shhi[bb*WP + k4*4]     = h01;
            *(__nv_bfloat162*)&shhi[bb*WP + k4*4 + 2] = h23;
            __nv_bfloat162 l01 = __floats2bfloat162_rn(v.x - __low2float(h01),
                                                       v.y - __high2float(h01));
            __nv_bfloat162 l23 = __floats2bfloat162_rn(v.z - __low2float(h23),
                                                       v.w - __high2float(h23));
            *(__nv_bfloat162*)&shlo[bb*WP + k4*4]     = l01;
            *(__nv_bfloat162*)&shlo[bb*WP + k4*4 + 2] = l23;
        }
        __syncthreads();

        float acc[3][2][4];
#pragma unroll
        for (int m = 0; m < 3; m++)
#pragma unroll
            for (int n = 0; n < 2; n++)
#pragma unroll
                for (int q = 0; q < 4; q++) acc[m][n][q] = 0.f;

#pragma unroll
        for (int i = 0; i < 7; i++){
            if (i < myNT){
                const uint32_t kb = (uint32_t)((kt0 + i)*16);
                uint32_t bh[4], bl[4], alo[4];
                ldm4(bh, uHhi + (uint32_t)((b_row*WP + kb + b_kg)*2));
                ldm4(bl, uHlo + (uint32_t)((b_row*WP + kb + b_kg)*2));
#pragma unroll
                for (int m = 0; m < 3; m++){
                    ldm4(alo, uWlo + (uint32_t)(((a_row + m*16)*WP + kb + a_kg)*2));
                    mma16816(acc[m][0], afr[m][i], &bh[0]);
                    mma16816(acc[m][1], afr[m][i], &bh[2]);
                    mma16816(acc[m][0], afr[m][i], &bl[0]);
                    mma16816(acc[m][1], afr[m][i], &bl[2]);
                    mma16816(acc[m][0], alo, &bh[0]);
                    mma16816(acc[m][1], alo, &bh[2]);
                }
            }
        }

        // 2-phase cross-warp reduction into fpart[4][768]
        const int prow = lane >> 2, pcol = (lane & 3)*2;
        if (warp < 4){
#pragma unroll
            for (int m = 0; m < 3; m++)
#pragma unroll
                for (int n = 0; n < 2; n++){
                    *(float2*)&fpart[warp*768 + (m*16 + prow)*16 + n*8 + pcol] =
                        make_float2(acc[m][n][0], acc[m][n][1]);
                    *(float2*)&fpart[warp*768 + (m*16 + prow + 8)*16 + n*8 + pcol] =
                        make_float2(acc[m][n][2], acc[m][n][3]);
                }
        }
        __syncthreads();
        if (warp >= 4){
            const int w4 = warp - 4;
#pragma unroll
            for (int m = 0; m < 3; m++)
#pragma unroll
                for (int n = 0; n < 2; n++){
                    float2* d0 = (float2*)&fpart[w4*768 + (m*16 + prow)*16 + n*8 + pcol];
                    float2 v0 = *d0; v0.x += acc[m][n][0]; v0.y += acc[m][n][1]; *d0 = v0;
                    float2* d1 = (float2*)&fpart[w4*768 + (m*16 + prow + 8)*16 + n*8 + pcol];
                    float2 v1 = *d1; v1.x += acc[m][n][2]; v1.y += acc[m][n][3]; *d1 = v1;
                }
        }
        __syncthreads();

        if (gateT){
            float giv = gi0, gf = gi1, gg = gi2, go = gi3;
#pragma unroll
            for (int pp = 0; pp < 4; pp++){
                giv += fpart[pp*768 + (guu*4 + 0)*16 + gbb];
                gf  += fpart[pp*768 + (guu*4 + 1)*16 + gbb];
                gg  += fpart[pp*768 + (guu*4 + 2)*16 + gbb];
                go  += fpart[pp*768 + (guu*4 + 3)*16 + gbb];
            }
            float c = sigf(gf)*sc[tid] + sigf(giv)*tanhf(gg);
            sc[tid] = c;
            float hv = sigf(go)*tanhf(c);
            int u = u0 + guu;
            g_hping[(((p^1)*2 + dir)*NB + gbb)*HN + u] = hv;
            hseq[(t*NB + gbb)*1600 + dir*HN + u] = hv;
        }
        p ^= 1;
        gbar(bar_base + 1 + s);
    }
}

// ---------------- bf16 split conversion kernels ------------------------------
__global__ void split_w_kernel(const float* __restrict__ w){
    const int n = 2*G4*1600;
    for (int i = blockIdx.x*256 + threadIdx.x; i < n; i += gridDim.x*256){
        float v = w[i];
        __nv_bfloat16 h = __float2bfloat16(v);
        g_whi[i] = h;
        g_wlo[i] = __float2bfloat16(v - __bfloat162float(h));
    }
}
__global__ void split_h_kernel(){
    const int n = 4096*1600;
    for (int i = blockIdx.x*256 + threadIdx.x; i < n; i += gridDim.x*256){
        float v = g_h1[i];
        __nv_bfloat16 h = __float2bfloat16(v);
        g_hhi[i] = h;
        g_hlo[i] = __float2bfloat16(v - __bfloat162float(h));
    }
}

// ---------------- kernel 3: layer-1 proj via mma.sync bf16-split ------------
#define TP 72
#define TILE_ELEMS (128*TP)
#define GEMM_SMEM (4*TILE_ELEMS*2)  // 73728 B
__global__ void __launch_bounds__(256) gemm1_mma(const float* __restrict__ bias){
    extern __shared__ __nv_bfloat16 gsm[];
    __nv_bfloat16* sAh = gsm;
    __nv_bfloat16* sAl = gsm + TILE_ELEMS;
    __nv_bfloat16* sBh = gsm + 2*TILE_ELEMS;
    __nv_bfloat16* sBl = gsm + 3*TILE_ELEMS;
    const uint32_t uAh = s2u(sAh), uAl = s2u(sAl), uBh = s2u(sBh), uBl = s2u(sBl);

    const int tid  = threadIdx.x;
    const int jt   = blockIdx.x, mt = blockIdx.y, dir = blockIdx.z;
    const int warp = tid >> 5, lane = tid & 31;
    const int wj   = warp & 1;
    const int wm   = warp >> 1;

    const __nv_bfloat16* Ahi = g_whi + ((size_t)dir*G4 + jt*128)*1600;
    const __nv_bfloat16* Alo = g_wlo + ((size_t)dir*G4 + jt*128)*1600;
    const __nv_bfloat16* Bhi = g_hhi + (size_t)(mt*128)*1600;
    const __nv_bfloat16* Blo = g_hlo + (size_t)(mt*128)*1600;

    float acc[4][4][4];
#pragma unroll
    for (int i = 0; i < 4; i++)
#pragma unroll
        for (int j = 0; j < 4; j++)
#pragma unroll
            for (int q = 0; q < 4; q++) acc[i][j][q] = 0.f;

    const int a_row = wj*64 + (lane & 15);
    const int a_kg  = (lane >> 4)*8;
    const int b_row = wm*32 + (lane & 7) + ((lane >> 4) & 1)*8;
    const int b_kg  = ((lane >> 3) & 1)*8;

    const int ldr = tid >> 1;
    const int ldg = (tid & 1)*4;

    for (int c = 0; c < 25; c++){
        const int k0 = c*64;
#pragma unroll
        for (int g = 0; g < 4; g++){
            int gg = ldg + g;
            size_t go = (size_t)ldr*1600 + k0 + gg*8;
            int so = ldr*TP + gg*8;
            *(float4*)&sAh[so] = *(const float4*)&Ahi[go];
            *(float4*)&sAl[so] = *(const float4*)&Alo[go];
            *(float4*)&sBh[so] = *(const float4*)&Bhi[go];
            *(float4*)&sBl[so] = *(const float4*)&Blo[go];
        }
        __syncthreads();
#pragma unroll
        for (int ks = 0; ks < 4; ks++){
            uint32_t ah[4][4], al[4][4], bh[2][4], bl[2][4];
#pragma unroll
            for (int i = 0; i < 4; i++){
                uint32_t off = (uint32_t)((a_row + i*16)*TP + ks*16 + a_kg)*2;
                ldm4(ah[i], uAh + off);
                ldm4(al[i], uAl + off);
            }
#pragma unroll
            for (int np = 0; np < 2; np++){
                uint32_t off = (uint32_t)((b_row + np*16)*TP + ks*16 + b_kg)*2;
                ldm4(bh[np], uBh + off);
                ldm4(bl[np], uBl + off);
            }
#pragma unroll
            for (int i = 0; i < 4; i++){
#pragma unroll
                for (int n = 0; n < 4; n++){
                    const uint32_t* bhp = &bh[n >> 1][(n & 1)*2];
                    const uint32_t* blp = &bl[n >> 1][(n & 1)*2];
                    mma16816(acc[i][n], ah[i], bhp);
                    mma16816(acc[i][n], ah[i], blp);
                    mma16816(acc[i][n], al[i], bhp);
                }
            }
        }
        __syncthreads();
    }

    const int jb = jt*128 + wj*64;
    const int mb = mt*128 + wm*32;
#pragma unroll
    for (int i = 0; i < 4; i++){
        int j0 = jb + i*16 + (lane >> 2);
        float bv0 = bias[dir*G4 + j0];
        float bv1 = bias[dir*G4 + j0 + 8];
        size_t r0 = (size_t)(dir*LSEQ)*G4;
#pragma unroll
        for (int n = 0; n < 4; n++){
            int m  = mb + n*8 + 2*(lane & 3);
            int t  = m >> 4, b2 = m & 15;
            float2 v0 = make_float2(acc[i][n][0] + bv0, acc[i][n][1] + bv0);
            float2 v1 = make_float2(acc[i][n][2] + bv1, acc[i][n][3] + bv1);
            *(float2*)&g_g1[(r0 + (size_t)t*G4 + j0)*NB + b2]     = v0;
            *(float2*)&g_g1[(r0 + (size_t)t*G4 + j0 + 8)*NB + b2] = v1;
        }
    }
}

// ---------------- kernel 4: head (logits -> softmax -> angles) --------------
__global__ void head_kernel(const float* __restrict__ wlin,
                            const float* __restrict__ blin,
                            const float* __restrict__ alphabet){
    const int t = blockIdx.x;
    const int tid = threadIdx.x;   // 320 threads
    __shared__ float slog[16][20];
    __shared__ float smax[16];
    __shared__ float sexp[16][20];
    __shared__ float ssin[20][3], scos[20][3];
    if (tid < 60){
        int a = tid / 3, i = tid - a*3;
        float v = alphabet[a*3 + i];
        ssin[a][i] = sinf(v); scos[a][i] = cosf(v);
    }
    const int a = tid % 20, b = tid / 20;
    float acc = blin[a];
    const float4* hr = (const float4*)&g_h2[((size_t)(t*NB + b))*1600];
    const float4* wr = (const float4*)&wlin[(size_t)a*1600];
    for (int k = 0; k < 400; k++){
        float4 h = hr[k], w = wr[k];
        acc = fmaf(h.x, w.x, acc); acc = fmaf(h.y, w.y, acc);
        acc = fmaf(h.z, w.z, acc); acc = fmaf(h.w, w.w, acc);
    }
    slog[b][a] = acc;
    __syncthreads();
    if (tid < 16){
        float m = -1e30f;
        for (int q = 0; q < 20; q++) m = fmaxf(m, slog[tid][q]);
        smax[tid] = m;
    }
    __syncthreads();
    sexp[b][a] = expf(slog[b][a] - smax[b]);
    __syncthreads();
    if (tid < 48){
        int bb = tid / 3, i = tid - bb*3;
        float s = 0.f, c = 0.f;
        for (int q = 0; q < 20; q++){
            float pv = sexp[bb][q];
            s = fmaf(pv, ssin[q][i], s);
            c = fmaf(pv, scos[q][i], c);
        }
        g_ang[(t*NB + bb)*3 + i] = atan2f(s, c);
    }
}

// ---------------- kernel 5: sequential coordinate chain (NeRF) --------------
__global__ void coords_kernel(float* __restrict__ out){
    const int b = threadIdx.x;
    if (b >= 16) return;
    const float Rv[3] = {145.801f, 152.326f, 132.868f};
    const float Tv[3] = {2.124f, 1.941f, 2.028f};
    float cT[3], sT[3];
#pragma unroll
    for (int i = 0; i < 3; i++){ cT[i] = cosf(Tv[i]); sT[i] = sinf(Tv[i]); }
    float Ax=0.f,Ay=0.f,Az=1.f, Bx=0.f,By=1.f,Bz=0.f, Cx=1.f,Cy=0.f,Cz=0.f;
    out[(0*16+b)*3+0]=0.f; out[(0*16+b)*3+1]=0.f; out[(0*16+b)*3+2]=1.f;
    out[(1*16+b)*3+0]=0.f; out[(1*16+b)*3+1]=1.f; out[(1*16+b)*3+2]=0.f;
    out[(2*16+b)*3+0]=1.f; out[(2*16+b)*3+1]=0.f; out[(2*16+b)*3+2]=0.f;
    for (int tt = 0; tt < LSEQ; tt++){
#pragma unroll
        for (int i = 0; i < 3; i++){
            float P = g_ang[(tt*NB + b)*3 + i];
            float sp, cp; sincosf(P, &sp, &cp);
            float d2x = -Rv[i]*cT[i];
            float d2y =  Rv[i]*cp*sT[i];
            float d2z =  Rv[i]*sp*sT[i];
            float bcx = Cx-Bx, bcy = Cy-By, bcz = Cz-Bz;
            float inv = rsqrtf(bcx*bcx + bcy*bcy + bcz*bcz);
            bcx *= inv; bcy *= inv; bcz *= inv;
            float abx = Bx-Ax, aby = By-Ay, abz = Bz-Az;
            float nx = aby*bcz - abz*bcy;
            float ny = abz*bcx - abx*bcz;
            float nz = abx*bcy - aby*bcx;
            float invn = rsqrtf(nx*nx + ny*ny + nz*nz);
            nx *= invn; ny *= invn; nz *= invn;
            float mx = ny*bcz - nz*bcy;
            float my = nz*bcx - nx*bcz;
            float mz = nx*bcy - ny*bcx;
            float Dx = bcx*d2x + mx*d2y + nx*d2z + Cx;
            float Dy = bcy*d2x + my*d2y + ny*d2z + Cy;
            float Dz = bcz*d2x + mz*d2y + nz*d2z + Cz;
            int row = 3 + tt*3 + i;
            out[(row*16 + b)*3 + 0] = Dx;
            out[(row*16 + b)*3 + 1] = Dy;
            out[(row*16 + b)*3 + 2] = Dz;
            Ax=Bx; Ay=By; Az=Bz;
            Bx=Cx; By=Cy; Bz=Cz;
            Cx=Dx; Cy=Dy; Cz=Dz;
        }
    }
}

// ---------------- launch ------------------------------------------------------
extern "C" void kernel_launch(void* const* d_in, const int* in_sizes, int n_in,
                              void* d_out, int out_size){
    const float* x    = (const float*)d_in[0];
    const float* wih0 = (const float*)d_in[1];
    const float* whh0 = (const float*)d_in[2];
    const float* b0   = (const float*)d_in[3];
    const float* wih1 = (const float*)d_in[4];
    const float* whh1 = (const float*)d_in[5];
    const float* b1   = (const float*)d_in[6];
    const float* wlin = (const float*)d_in[7];
    const float* blin = (const float*)d_in[8];
    const float* alph = (const float*)d_in[9];
    float* out = (float*)d_out;

    cudaFuncSetAttribute(lstm_mma_kernel,
                         cudaFuncAttributeMaxDynamicSharedMemorySize,
                         LSTM_MMA_SMEM);
    cudaFuncSetAttribute(gemm1_mma,
                         cudaFuncAttributeMaxDynamicSharedMemorySize,
                         GEMM_SMEM);

    proj0_kernel<<<dim3(LSEQ,2),256>>>(x, wih0, b0);               // + barrier reset
    split_w_kernel<<<1024,256>>>(wih1);
    lstm_mma_kernel<<<NCTA,256,LSTM_MMA_SMEM>>>(whh0, 0, 0);       // slots 0..257
    split_h_kernel<<<1024,256>>>();
    gemm1_mma<<<dim3(25,32,2),256,GEMM_SMEM>>>(b1);
    lstm_mma_kernel<<<NCTA,256,LSTM_MMA_SMEM>>>(whh1, 1, 300);     // slots 300..557
    head_kernel<<<LSEQ,320>>>(wlin, blin, alph);
    coords_kernel<<<1,32>>>(out);
}

// round 16
// speedup vs baseline: 2.4304x; 1.0264x over previous
#include <cuda_runtime.h>
#include <cuda_bf16.h>
#include <math.h>
#include <stdint.h>

// D_IN=42, H=800, L=256, B=16, ALPHA=20
#define LSEQ 256
#define HN   800
#define NB   16
#define G4   3200
#define NCTA 148
#define CPD  74
#define WP   808                      // smem pitch (bf16): 1616B = 101*16 (LDSM-legal), conflict-free
#define LSTM_MMA_SMEM (128*WP*2 + 4*768*4 + 176*4)   // 219840 B

// ---------------- scratch (device globals; no allocations allowed) ----------
static __device__ float g_g0[2*LSEQ*G4*NB];
static __device__ float g_g1[2*LSEQ*G4*NB];
static __device__ float g_h2[LSEQ*NB*1600];
static __device__ unsigned g_hpack[2*2*NB*HN];    // packed (hi,lo) bf16 per unit
static __device__ float g_ang[LSEQ*NB*3];
static __device__ unsigned g_bar[2048];           // [dir*1024 + slot] counters
// bf16-split operands for tensor-core gemm1
static __device__ __nv_bfloat16 g_whi[2*G4*1600];
static __device__ __nv_bfloat16 g_wlo[2*G4*1600];
static __device__ __nv_bfloat16 g_hhi[4096*1600];
static __device__ __nv_bfloat16 g_hlo[4096*1600];

__device__ __forceinline__ float sigf(float x){ return 1.0f/(1.0f+expf(-x)); }

__device__ __forceinline__ uint32_t s2u(const void* p){
    uint32_t a;
    asm("{ .reg .u64 t; cvta.to.shared.u64 t, %1; cvt.u32.u64 %0, t; }"
        : "=r"(a) : "l"(p));
    return a;
}
__device__ __forceinline__ void ldm4(uint32_t* r, uint32_t addr){
    asm volatile("ldmatrix.sync.aligned.m8n8.x4.shared.b16 {%0,%1,%2,%3}, [%4];"
        : "=r"(r[0]),"=r"(r[1]),"=r"(r[2]),"=r"(r[3]) : "r"(addr));
}
__device__ __forceinline__ void mma16816(float* d, const uint32_t* a, const uint32_t* b){
    asm volatile("mma.sync.aligned.m16n8k16.row.col.f32.bf16.bf16.f32 "
        "{%0,%1,%2,%3}, {%4,%5,%6,%7}, {%8,%9}, {%0,%1,%2,%3};"
        : "+f"(d[0]),"+f"(d[1]),"+f"(d[2]),"+f"(d[3])
        : "r"(a[0]),"r"(a[1]),"r"(a[2]),"r"(a[3]), "r"(b[0]),"r"(b[1]));
}

// ---------------- per-direction grid barrier (R11 mechanics, 74 arrivals) ---
__device__ __forceinline__ void gbar2(int dir, int idx){
    __syncthreads();
    if (threadIdx.x == 0){
        __threadfence();
        unsigned* ctr = &g_bar[dir*1024 + idx];
        atomicAdd(ctr, 1u);
        volatile unsigned* vb = ctr;
        while (*vb < (unsigned)CPD) { }
        __threadfence();
    }
    __syncthreads();
}

// ---------------- kernel 1: layer-0 input projection (K=42) -----------------
__global__ void proj0_kernel(const float* __restrict__ x,
                             const float* __restrict__ wih,
                             const float* __restrict__ bias){
    const int t = blockIdx.x, dir = blockIdx.y;
    const int tid = threadIdx.x;
    __shared__ float sx[16*42];
    if (t == 0 && dir == 0){
        for (int i = tid; i < 2048; i += 256) g_bar[i] = 0u;
    }
    for (int i = tid; i < 16*42; i += 256){
        int bb = i / 42, d = i - bb*42;
        sx[i] = x[(bb*LSEQ + t)*42 + d];
    }
    __syncthreads();
    for (int j = tid; j < G4; j += 256){
        const float* w = &wih[(dir*G4 + j)*42];
        float wr[42];
#pragma unroll
        for (int d = 0; d < 42; d++) wr[d] = w[d];
        float bv = bias[dir*G4 + j];
        float* gout = &g_g0[(((size_t)dir*LSEQ + t)*G4 + j)*NB];
        for (int bb = 0; bb < 16; bb++){
            float acc = bv;
#pragma unroll
            for (int d = 0; d < 42; d++) acc = fmaf(wr[d], sx[bb*42 + d], acc);
            gout[bb] = acc;
        }
    }
}

// ---------------- kernel 2: persistent bi-LSTM via mma.sync bf16-split ------
// 148 CTAs; CTA owns 10-11 units (40-44 gate rows, padded to 48).
// h carried as packed (hi,lo) bf16; per-direction barriers; arrive-early with
// non-critical stores overlapped into the poll window.
__global__ void __launch_bounds__(256,1) lstm_mma_kernel(
    const float* __restrict__ whh, int layer, int bar_base)
{
    extern __shared__ char dsm8[];
    __nv_bfloat16* swhi = (__nv_bfloat16*)dsm8;
    __nv_bfloat16* swlo = swhi + 48*WP;
    __nv_bfloat16* shhi = swhi + 96*WP;
    __nv_bfloat16* shlo = swhi + 112*WP;
    float* fpart = (float*)(dsm8 + 128*WP*2);    // [4][768]
    float* sc    = fpart + 4*768;                // [176]

    const float* gin = layer ? g_g1 : g_g0;

    const int cta = blockIdx.x;
    const int dir = cta / CPD;
    const int lc  = cta - dir*CPD;
    const int u0  = (lc*HN)/CPD;
    const int n_u = ((lc+1)*HN)/CPD - u0;
    const int n_rows = 4*n_u;
    const int tid = threadIdx.x;
    const int lane = tid & 31, warp = tid >> 5;

    // one-time: weights -> smem bf16 hi/lo (rows >= n_rows zeroed)
    for (int i = tid; i < 48*200; i += 256){
        int r = i/200, k4 = i - r*200;
        float4 v = make_float4(0.f,0.f,0.f,0.f);
        if (r < n_rows){
            int q = r & 3, uu = r >> 2;
            int j = q*HN + u0 + uu;
            v = *(const float4*)&whh[((size_t)(dir*G4 + j))*HN + k4*4];
        }
        __nv_bfloat162 h01 = __floats2bfloat162_rn(v.x, v.y);
        __nv_bfloat162 h23 = __floats2bfloat162_rn(v.z, v.w);
        *(__nv_bfloat162*)&swhi[r*WP + k4*4]     = h01;
        *(__nv_bfloat162*)&swhi[r*WP + k4*4 + 2] = h23;
        __nv_bfloat162 l01 = __floats2bfloat162_rn(v.x - __low2float(h01),
                                                   v.y - __high2float(h01));
        __nv_bfloat162 l23 = __floats2bfloat162_rn(v.z - __low2float(h23),
                                                   v.w - __high2float(h23));
        *(__nv_bfloat162*)&swlo[r*WP + k4*4]     = l01;
        *(__nv_bfloat162*)&swlo[r*WP + k4*4 + 2] = l23;
    }
    if (tid < n_u*16){
        sc[tid] = 0.f;
        g_hpack[(dir*NB + (tid & 15))*HN + u0 + (tid >> 4)] = 0u;
    }
    gbar2(dir, bar_base);   // weight smem + init visible

    const uint32_t uWhi = s2u(swhi), uWlo = s2u(swlo);
    const uint32_t uHhi = s2u(shhi), uHlo = s2u(shlo);
    const int a_row = lane & 15;
    const int a_kg  = (lane >> 4)*8;
    const int b_row = (lane & 7) + ((lane >> 4) & 1)*8;
    const int b_kg  = ((lane >> 3) & 1)*8;
    const int myNT  = (warp < 2) ? 7 : 6;
    const int kt0   = (warp < 2) ? warp*7 : 14 + (warp - 2)*6;

    // A_hi fragments, register-resident for all 256 steps
    uint32_t afr[3][7][4];
#pragma unroll
    for (int m = 0; m < 3; m++)
#pragma unroll
        for (int i = 0; i < 7; i++)
            if (i < myNT)
                ldm4(afr[m][i],
                     uWhi + (uint32_t)(((a_row + m*16)*WP + (kt0+i)*16 + a_kg)*2));

    const int guu = tid >> 4, gbb = tid & 15;
    const bool gateT = tid < n_u*16;

    int p = 0;
    for (int s = 0; s < LSEQ; s++){
        const int t = dir ? (LSEQ-1-s) : s;
        // prefetch input projections (consumed in gate phase)
        float gi0=0.f, gi1=0.f, gi2=0.f, gi3=0.f;
        if (gateT){
            const float* gi = gin + ((size_t)(dir*LSEQ + t)*G4)*NB;
            size_t jb = (size_t)(u0 + guu);
            gi0 = gi[(0*HN + jb)*NB + gbb];
            gi1 = gi[(1*HN + jb)*NB + gbb];
            gi2 = gi[(2*HN + jb)*NB + gbb];
            gi3 = gi[(3*HN + jb)*NB + gbb];
        }
        // fill: packed (hi,lo) -> smem via byte_perm (no conversions)
        for (int idx = tid; idx < 3200; idx += 256){
            int bb = idx/200, k4 = idx - bb*200;
            uint4 w = __ldcg((const uint4*)&g_hpack[((p*2 + dir)*NB + bb)*HN + k4*4]);
            unsigned hi01 = __byte_perm(w.x, w.y, 0x5410);
            unsigned hi23 = __byte_perm(w.z, w.w, 0x5410);
            unsigned lo01 = __byte_perm(w.x, w.y, 0x7632);
            unsigned lo23 = __byte_perm(w.z, w.w, 0x7632);
            *(uint2*)&shhi[bb*WP + k4*4] = make_uint2(hi01, hi23);
            *(uint2*)&shlo[bb*WP + k4*4] = make_uint2(lo01, lo23);
        }
        __syncthreads();

        float acc[3][2][4];
#pragma unroll
        for (int m = 0; m < 3; m++)
#pragma unroll
            for (int n = 0; n < 2; n++)
#pragma unroll
                for (int q = 0; q < 4; q++) acc[m][n][q] = 0.f;

#pragma unroll
        for (int i = 0; i < 7; i++){
            if (i < myNT){
                const uint32_t kb = (uint32_t)((kt0 + i)*16);
                uint32_t bh[4], bl[4], alo[4];
                ldm4(bh, uHhi + (uint32_t)((b_row*WP + kb + b_kg)*2));
                ldm4(bl, uHlo + (uint32_t)((b_row*WP + kb + b_kg)*2));
#pragma unroll
                for (int m = 0; m < 3; m++){
                    ldm4(alo, uWlo + (uint32_t)(((a_row + m*16)*WP + kb + a_kg)*2));
                    mma16816(acc[m][0], afr[m][i], &bh[0]);
                    mma16816(acc[m][1], afr[m][i], &bh[2]);
                    mma16816(acc[m][0], afr[m][i], &bl[0]);
                    mma16816(acc[m][1], afr[m][i], &bl[2]);
                    mma16816(acc[m][0], alo, &bh[0]);
                    mma16816(acc[m][1], alo, &bh[2]);
                }
            }
        }

        // 2-phase cross-warp reduction into fpart[4][768]
        const int prow = lane >> 2, pcol = (lane & 3)*2;
        if (warp < 4){
#pragma unroll
            for (int m = 0; m < 3; m++)
#pragma unroll
                for (int n = 0; n < 2; n++){
                    *(float2*)&fpart[warp*768 + (m*16 + prow)*16 + n*8 + pcol] =
                        make_float2(acc[m][n][0], acc[m][n][1]);
                    *(float2*)&fpart[warp*768 + (m*16 + prow + 8)*16 + n*8 + pcol] =
                        make_float2(acc[m][n][2], acc[m][n][3]);
                }
        }
        __syncthreads();
        if (warp >= 4){
            const int w4 = warp - 4;
#pragma unroll
            for (int m = 0; m < 3; m++)
#pragma unroll
                for (int n = 0; n < 2; n++){
                    float2* d0 = (float2*)&fpart[w4*768 + (m*16 + prow)*16 + n*8 + pcol];
                    float2 v0 = *d0; v0.x += acc[m][n][0]; v0.y += acc[m][n][1]; *d0 = v0;
                    float2* d1 = (float2*)&fpart[w4*768 + (m*16 + prow + 8)*16 + n*8 + pcol];
                    float2 v1 = *d1; v1.x += acc[m][n][2]; v1.y += acc[m][n][3]; *d1 = v1;
                }
        }
        __syncthreads();

        // gates: compute, store ONLY hpack before arrival
        float hv = 0.f;
        __nv_bfloat16 hib, lob;
        if (gateT){
            float giv = gi0, gf = gi1, gg = gi2, go = gi3;
#pragma unroll
            for (int pp = 0; pp < 4; pp++){
                giv += fpart[pp*768 + (guu*4 + 0)*16 + gbb];
                gf  += fpart[pp*768 + (guu*4 + 1)*16 + gbb];
                gg  += fpart[pp*768 + (guu*4 + 2)*16 + gbb];
                go  += fpart[pp*768 + (guu*4 + 3)*16 + gbb];
            }
            float c = sigf(gf)*sc[tid] + sigf(giv)*tanhf(gg);
            sc[tid] = c;
            hv = sigf(go)*tanhf(c);
            hib = __float2bfloat16(hv);
            lob = __float2bfloat16(hv - __bfloat162float(hib));
            unsigned short hs = *(unsigned short*)&hib;
            unsigned short ls = *(unsigned short*)&lob;
            unsigned word = (unsigned)hs | ((unsigned)ls << 16);
            g_hpack[(((p^1)*2 + dir)*NB + gbb)*HN + (u0 + guu)] = word;
        }
        __syncthreads();
        unsigned* ctr = &g_bar[dir*1024 + bar_base + 1 + s];
        if (tid == 0){
            __threadfence();
            atomicAdd(ctr, 1u);
        }
        // overlap window: non-critical stores while other CTAs arrive
        if (gateT){
            int u = u0 + guu;
            size_t ofs = (size_t)(t*NB + gbb)*1600 + dir*HN + u;
            if (layer == 0){
                g_hhi[ofs] = hib;
                g_hlo[ofs] = lob;
            } else {
                g_h2[ofs] = hv;
            }
        }
        if (tid == 0){
            volatile unsigned* vb = ctr;
            while (*vb < (unsigned)CPD) { }
            __threadfence();
        }
        __syncthreads();
        p ^= 1;
    }
}

// ---------------- bf16 split conversion for wih1 -----------------------------
__global__ void split_w_kernel(const float* __restrict__ w){
    const int n = 2*G4*1600;
    for (int i = blockIdx.x*256 + threadIdx.x; i < n; i += gridDim.x*256){
        float v = w[i];
        __nv_bfloat16 h = __float2bfloat16(v);
        g_whi[i] = h;
        g_wlo[i] = __float2bfloat16(v - __bfloat162float(h));
    }
}

// ---------------- kernel 3: layer-1 proj via mma.sync bf16-split ------------
#define TP 72
#define TILE_ELEMS (128*TP)
#define GEMM_SMEM (4*TILE_ELEMS*2)  // 73728 B
__global__ void __launch_bounds__(256) gemm1_mma(const float* __restrict__ bias){
    extern __shared__ __nv_bfloat16 gsm[];
    __nv_bfloat16* sAh = gsm;
    __nv_bfloat16* sAl = gsm + TILE_ELEMS;
    __nv_bfloat16* sBh = gsm + 2*TILE_ELEMS;
    __nv_bfloat16* sBl = gsm + 3*TILE_ELEMS;
    const uint32_t uAh = s2u(sAh), uAl = s2u(sAl), uBh = s2u(sBh), uBl = s2u(sBl);

    const int tid  = threadIdx.x;
    const int jt   = blockIdx.x, mt = blockIdx.y, dir = blockIdx.z;
    const int warp = tid >> 5, lane = tid & 31;
    const int wj   = warp & 1;
    const int wm   = warp >> 1;

    const __nv_bfloat16* Ahi = g_whi + ((size_t)dir*G4 + jt*128)*1600;
    const __nv_bfloat16* Alo = g_wlo + ((size_t)dir*G4 + jt*128)*1600;
    const __nv_bfloat16* Bhi = g_hhi + (size_t)(mt*128)*1600;
    const __nv_bfloat16* Blo = g_hlo + (size_t)(mt*128)*1600;

    float acc[4][4][4];
#pragma unroll
    for (int i = 0; i < 4; i++)
#pragma unroll
        for (int j = 0; j < 4; j++)
#pragma unroll
            for (int q = 0; q < 4; q++) acc[i][j][q] = 0.f;

    const int a_row = wj*64 + (lane & 15);
    const int a_kg  = (lane >> 4)*8;
    const int b_row = wm*32 + (lane & 7) + ((lane >> 4) & 1)*8;
    const int b_kg  = ((lane >> 3) & 1)*8;

    const int ldr = tid >> 1;
    const int ldg = (tid & 1)*4;

    for (int c = 0; c < 25; c++){
        const int k0 = c*64;
#pragma unroll
        for (int g = 0; g < 4; g++){
            int gg = ldg + g;
            size_t go = (size_t)ldr*1600 + k0 + gg*8;
            int so = ldr*TP + gg*8;
            *(float4*)&sAh[so] = *(const float4*)&Ahi[go];
            *(float4*)&sAl[so] = *(const float4*)&Alo[go];
            *(float4*)&sBh[so] = *(const float4*)&Bhi[go];
            *(float4*)&sBl[so] = *(const float4*)&Blo[go];
        }
        __syncthreads();
#pragma unroll
        for (int ks = 0; ks < 4; ks++){
            uint32_t ah[4][4], al[4][4], bh[2][4], bl[2][4];
#pragma unroll
            for (int i = 0; i < 4; i++){
                uint32_t off = (uint32_t)((a_row + i*16)*TP + ks*16 + a_kg)*2;
                ldm4(ah[i], uAh + off);
                ldm4(al[i], uAl + off);
            }
#pragma unroll
            for (int np = 0; np < 2; np++){
                uint32_t off = (uint32_t)((b_row + np*16)*TP + ks*16 + b_kg)*2;
                ldm4(bh[np], uBh + off);
                ldm4(bl[np], uBl + off);
            }
#pragma unroll
            for (int i = 0; i < 4; i++){
#pragma unroll
                for (int n = 0; n < 4; n++){
                    const uint32_t* bhp = &bh[n >> 1][(n & 1)*2];
                    const uint32_t* blp = &bl[n >> 1][(n & 1)*2];
                    mma16816(acc[i][n], ah[i], bhp);
                    mma16816(acc[i][n], ah[i], blp);
                    mma16816(acc[i][n], al[i], bhp);
                }
            }
        }
        __syncthreads();
    }

    const int jb = jt*128 + wj*64;
    const int mb = mt*128 + wm*32;
#pragma unroll
    for (int i = 0; i < 4; i++){
        int j0 = jb + i*16 + (lane >> 2);
        float bv0 = bias[dir*G4 + j0];
        float bv1 = bias[dir*G4 + j0 + 8];
        size_t r0 = (size_t)(dir*LSEQ)*G4;
#pragma unroll
        for (int n = 0; n < 4; n++){
            int m  = mb + n*8 + 2*(lane & 3);
            int t  = m >> 4, b2 = m & 15;
            float2 v0 = make_float2(acc[i][n][0] + bv0, acc[i][n][1] + bv0);
            float2 v1 = make_float2(acc[i][n][2] + bv1, acc[i][n][3] + bv1);
            *(float2*)&g_g1[(r0 + (size_t)t*G4 + j0)*NB + b2]     = v0;
            *(float2*)&g_g1[(r0 + (size_t)t*G4 + j0 + 8)*NB + b2] = v1;
        }
    }
}

// ---------------- kernel 4: head (logits -> softmax -> angles) --------------
__global__ void head_kernel(const float* __restrict__ wlin,
                            const float* __restrict__ blin,
                            const float* __restrict__ alphabet){
    const int t = blockIdx.x;
    const int tid = threadIdx.x;   // 320 threads
    __shared__ float slog[16][20];
    __shared__ float smax[16];
    __shared__ float sexp[16][20];
    __shared__ float ssin[20][3], scos[20][3];
    if (tid < 60){
        int a = tid / 3, i = tid - a*3;
        float v = alphabet[a*3 + i];
        ssin[a][i] = sinf(v); scos[a][i] = cosf(v);
    }
    const int a = tid % 20, b = tid / 20;
    float acc = blin[a];
    const float4* hr = (const float4*)&g_h2[((size_t)(t*NB + b))*1600];
    const float4* wr = (const float4*)&wlin[(size_t)a*1600];
    for (int k = 0; k < 400; k++){
        float4 h = hr[k], w = wr[k];
        acc = fmaf(h.x, w.x, acc); acc = fmaf(h.y, w.y, acc);
        acc = fmaf(h.z, w.z, acc); acc = fmaf(h.w, w.w, acc);
    }
    slog[b][a] = acc;
    __syncthreads();
    if (tid < 16){
        float m = -1e30f;
        for (int q = 0; q < 20; q++) m = fmaxf(m, slog[tid][q]);
        smax[tid] = m;
    }
    __syncthreads();
    sexp[b][a] = expf(slog[b][a] - smax[b]);
    __syncthreads();
    if (tid < 48){
        int bb = tid / 3, i = tid - bb*3;
        float s = 0.f, c = 0.f;
        for (int q = 0; q < 20; q++){
            float pv = sexp[bb][q];
            s = fmaf(pv, ssin[q][i], s);
            c = fmaf(pv, scos[q][i], c);
        }
        g_ang[(t*NB + bb)*3 + i] = atan2f(s, c);
    }
}

// ---------------- kernel 5: sequential coordinate chain (NeRF) --------------
__global__ void coords_kernel(float* __restrict__ out){
    const int b = threadIdx.x;
    if (b >= 16) return;
    const float Rv[3] = {145.801f, 152.326f, 132.868f};
    const float Tv[3] = {2.124f, 1.941f, 2.028f};
    float cT[3], sT[3];
#pragma unroll
    for (int i = 0; i < 3; i++){ cT[i] = cosf(Tv[i]); sT[i] = sinf(Tv[i]); }
    float Ax=0.f,Ay=0.f,Az=1.f, Bx=0.f,By=1.f,Bz=0.f, Cx=1.f,Cy=0.f,Cz=0.f;
    out[(0*16+b)*3+0]=0.f; out[(0*16+b)*3+1]=0.f; out[(0*16+b)*3+2]=1.f;
    out[(1*16+b)*3+0]=0.f; out[(1*16+b)*3+1]=1.f; out[(1*16+b)*3+2]=0.f;
    out[(2*16+b)*3+0]=1.f; out[(2*16+b)*3+1]=0.f; out[(2*16+b)*3+2]=0.f;
    for (int tt = 0; tt < LSEQ; tt++){
#pragma unroll
        for (int i = 0; i < 3; i++){
            float P = g_ang[(tt*NB + b)*3 + i];
            float sp, cp; sincosf(P, &sp, &cp);
            float d2x = -Rv[i]*cT[i];
            float d2y =  Rv[i]*cp*sT[i];
            float d2z =  Rv[i]*sp*sT[i];
            float bcx = Cx-Bx, bcy = Cy-By, bcz = Cz-Bz;
            float inv = rsqrtf(bcx*bcx + bcy*bcy + bcz*bcz);
            bcx *= inv; bcy *= inv; bcz *= inv;
            float abx = Bx-Ax, aby = By-Ay, abz = Bz-Az;
            float nx = aby*bcz - abz*bcy;
            float ny = abz*bcx - abx*bcz;
            float nz = abx*bcy - aby*bcx;
            float invn = rsqrtf(nx*nx + ny*ny + nz*nz);
            nx *= invn; ny *= invn; nz *= invn;
            float mx = ny*bcz - nz*bcy;
            float my = nz*bcx - nx*bcz;
            float mz = nx*bcy - ny*bcx;
            float Dx = bcx*d2x + mx*d2y + nx*d2z + Cx;
            float Dy = bcy*d2x + my*d2y + ny*d2z + Cy;
            float Dz = bcz*d2x + mz*d2y + nz*d2z + Cz;
            int row = 3 + tt*3 + i;
            out[(row*16 + b)*3 + 0] = Dx;
            out[(row*16 + b)*3 + 1] = Dy;
            out[(row*16 + b)*3 + 2] = Dz;
            Ax=Bx; Ay=By; Az=Bz;
            Bx=Cx; By=Cy; Bz=Cz;
            Cx=Dx; Cy=Dy; Cz=Dz;
        }
    }
}

// ---------------- launch ------------------------------------------------------
extern "C" void kernel_launch(void* const* d_in, const int* in_sizes, int n_in,
                              void* d_out, int out_size){
    const float* x    = (const float*)d_in[0];
    const float* wih0 = (const float*)d_in[1];
    const float* whh0 = (const float*)d_in[2];
    const float* b0   = (const float*)d_in[3];
    const float* wih1 = (const float*)d_in[4];
    const float* whh1 = (const float*)d_in[5];
    const float* b1   = (const float*)d_in[6];
    const float* wlin = (const float*)d_in[7];
    const float* blin = (const float*)d_in[8];
    const float* alph = (const float*)d_in[9];
    float* out = (float*)d_out;

    cudaFuncSetAttribute(lstm_mma_kernel,
                         cudaFuncAttributeMaxDynamicSharedMemorySize,
                         LSTM_MMA_SMEM);
    cudaFuncSetAttribute(gemm1_mma,
                         cudaFuncAttributeMaxDynamicSharedMemorySize,
                         GEMM_SMEM);

    proj0_kernel<<<dim3(LSEQ,2),256>>>(x, wih0, b0);               // + counter reset
    split_w_kernel<<<1024,256>>>(wih1);
    lstm_mma_kernel<<<NCTA,256,LSTM_MMA_SMEM>>>(whh0, 0, 0);       // slots 0..257/dir
    gemm1_mma<<<dim3(25,32,2),256,GEMM_SMEM>>>(b1);
    lstm_mma_kernel<<<NCTA,256,LSTM_MMA_SMEM>>>(whh1, 1, 300);     // slots 300..557/dir
    head_kernel<<<LSEQ,320>>>(wlin, blin, alph);
    coords_kernel<<<1,32>>>(out);
}